// round 6
// baseline (speedup 1.0000x reference)
#include <cuda_runtime.h>
#include <math.h>

// NarrowParabolicEq — precomputed banded step operator.
// Dopri5 step = S = P + iQ, P = I - c2*Z^2 + c4*Z^4 - c6*Z^6 (real, radius 6),
// Q = Z - c3*Z^3 + c5*Z^5 (real, radius 5), Z = real tridiagonal h*zeta.
// Rows of P,Q recovered exactly by 13 comb-vector Horner runs (band width 13
// == comb period; each thread's comb output IS its row entry). Main loop:
// one 13-pt banded apply + ONE barrier per RK step (2000 barriers total).
// 512 threads, 1 point/thread, packed f32x2, dual shifted Y copies for
// alignment-uniform LDS.128 halo loads. Planar complex output.

#define NPTS 500
#define NTH  512
#define YSLOTS 528        // point q -> slot q+6 (copy0) / q+7 (copy1)
#define ZSLOTS (NTH + 2)
#define N_INNER 10

typedef unsigned long long u64;
union F2U { float2 f; u64 u; };

__device__ __forceinline__ u64 pk2(float lo, float hi) { F2U x; x.f.x = lo; x.f.y = hi; return x.u; }
__device__ __forceinline__ float lo2(u64 v) { F2U a; a.u = v; return a.f.x; }
__device__ __forceinline__ float hi2(u64 v) { F2U a; a.u = v; return a.f.y; }

__device__ __forceinline__ u64 fma2(u64 a, u64 b, u64 c)
{ u64 d; asm("fma.rn.f32x2 %0,%1,%2,%3;" : "=l"(d) : "l"(a), "l"(b), "l"(c)); return d; }
__device__ __forceinline__ u64 add2(u64 a, u64 b)
{ u64 d; asm("add.rn.f32x2 %0,%1,%2;" : "=l"(d) : "l"(a), "l"(b)); return d; }
__device__ __forceinline__ u64 mul2(u64 a, u64 b)
{ u64 d; asm("mul.rn.f32x2 %0,%1,%2;" : "=l"(d) : "l"(a), "l"(b)); return d; }

__device__ __forceinline__ void coeffs_at(int q, double K0d, double refc, double refd,
                                          float* hcli, float* hch2)
{
    if (q >= 1 && q <= NPTS - 2) {
        double dx = 2000.0 / 499.0;
        double cli = (1.0 / (dx * dx)) / (2.0 * K0d);
        double z  = 2000.0 * (double)q / 499.0;
        double zz = 2.0 * (z - refd) / refd;
        double c  = refc * (1.0 + 0.00737 * (zz - 1.0 + exp(-zz)));
        double het = (1500.0 / c) * (1500.0 / c) - 1.0;
        double ch = K0d * het;
        *hcli = (float)(0.1 * cli);
        *hch2 = (float)(0.1 * (ch - 2.0 * cli));
    } else {
        *hcli = 0.0f; *hch2 = 0.0f;
    }
}

__global__ __launch_bounds__(NTH, 1)
void pe_kernel(const float* __restrict__ params, float* __restrict__ out, int n_save)
{
    __shared__ __align__(16) u64 YA0[YSLOTS];
    __shared__ __align__(16) u64 YA1[YSLOTS];
    __shared__ __align__(16) u64 YB0[YSLOTS];
    __shared__ __align__(16) u64 YB1[YSLOTS];
    __shared__ float ZA[ZSLOTS];
    __shared__ float ZB[ZSLOTS];

    const int p = threadIdx.x;
    const int half = n_save * NPTS;

    const double PI  = 3.14159265358979323846;
    const double K0d = 2.0 * PI * 50.0 / 1500.0;
    const double refc = (double)params[0];
    const double refd = (double)params[1];

    float hcli, hch2;
    coeffs_at(p, K0d, refc, refd, &hcli, &hch2);

    // ---- initial field ----
    float y0r = 0.f;
    if (p < NPTS) {
        double ww  = sqrt(2.0 * log(2.0)) / (K0d * sin(PI / 180.0 * 1.5));
        double amp = 1.0 / (sqrt(PI) * ww);
        double z = 2000.0 * (double)p / 499.0;
        double a = (z - 100.0) / ww;
        y0r = (float)(amp * exp(-a * a));
        out[p] = y0r;            // row 0, real plane
        out[half + p] = 0.f;     // row 0, imag plane
    }

    // ---------- precompute P,Q band rows via 13 comb runs ----------
    float PcL[13], QcL[13];
    #pragma unroll
    for (int j = 0; j < 13; j++) { PcL[j] = 0.f; QcL[j] = 0.f; }

    if (p == 0) { ZA[0]=0.f; ZA[ZSLOTS-1]=0.f; ZB[0]=0.f; ZB[ZSLOTS-1]=0.f; }

    const float c2 = 0.5f;
    const float c3 = (float)(1.0/6.0);
    const float c4 = (float)(1.0/24.0);
    const float c5 = (float)(1.0/120.0);
    const float c6 = (float)(1.0/600.0);
    const int pm = p % 13;

    for (int r = 0; r < 13; r++) {
        float e = (pm == r) ? 1.f : 0.f;
        ZA[p + 1] = e;
        __syncthreads();
        float Pa = e, Qa = 0.f;         // c0 = 1
        float* cur = ZA; float* nxt = ZB;
        #pragma unroll
        for (int k = 1; k <= 6; k++) {
            float zk = hcli * (cur[p] + cur[p + 2]) + hch2 * cur[p + 1];
            nxt[p + 1] = zk;
            __syncthreads();
            if      (k == 1) Qa += zk;
            else if (k == 2) Pa -= c2 * zk;
            else if (k == 3) Qa -= c3 * zk;
            else if (k == 4) Pa += c4 * zk;
            else if (k == 5) Qa += c5 * zk;
            else             Pa -= c6 * zk;
            float* t_ = cur; cur = nxt; nxt = t_;
        }
        // comb r holds row entry at offset o where (p+o) === r (mod 13)
        int o = r - pm; if (o < -6) o += 13; else if (o > 6) o -= 13;
        PcL[o + 6] = Pa;
        QcL[o + 6] = Qa;
    }

    u64 Pc[13], Qc[11];
    #pragma unroll
    for (int j = 0; j < 13; j++) Pc[j] = pk2(PcL[j], PcL[j]);
    #pragma unroll
    for (int j = 0; j < 11; j++) Qc[j] = pk2(QcL[j + 1], QcL[j + 1]);   // offsets -5..5

    // ---------- Y buffers ----------
    for (int j = p; j < YSLOTS; j += NTH) { YA0[j]=0; YA1[j]=0; YB0[j]=0; YB1[j]=0; }
    __syncthreads();
    u64 y = pk2(y0r, 0.f);
    YA0[p + 6] = y;     // copy0: point q at slot q+6
    YA1[p + 7] = y;     // copy1: shifted one u64 for odd-thread alignment
    __syncthreads();

    u64 *cur0 = YA0, *cur1 = YA1, *nx0 = YB0, *nx1 = YB1;
    const int nitv = n_save - 1;

    for (int itv = 0; itv < nitv; ++itv) {
        #pragma unroll 1
        for (int st = 0; st < N_INNER; ++st) {
            // halo: points p-6..p+7 -> 7 aligned LDS.128
            const float4* B = (p & 1)
                ? ((const float4*)cur1) + ((p + 1) >> 1)
                : ((const float4*)cur0) + (p >> 1);
            u64 v[14];
            #pragma unroll
            for (int j = 0; j < 7; j++) {
                float4 f = B[j];
                v[2*j]     = pk2(f.x, f.y);
                v[2*j + 1] = pk2(f.z, f.w);
            }
            // (P y): offsets -6..6 = Pc[j] * v[j]
            u64 a0 = mul2(Pc[0], v[0]);
            u64 a1 = mul2(Pc[1], v[1]);
            #pragma unroll
            for (int j = 2; j < 13; j += 2) a0 = fma2(Pc[j], v[j], a0);
            #pragma unroll
            for (int j = 3; j < 13; j += 2) a1 = fma2(Pc[j], v[j], a1);
            // (Q y): offsets -5..5 = Qc[j] * v[j+1]
            u64 q0 = mul2(Qc[0], v[1]);
            u64 q1 = mul2(Qc[1], v[2]);
            #pragma unroll
            for (int j = 2; j < 11; j += 2) q0 = fma2(Qc[j], v[j + 1], q0);
            #pragma unroll
            for (int j = 3; j < 11; j += 2) q1 = fma2(Qc[j], v[j + 1], q1);

            u64 up = add2(a0, a1);
            u64 uq = add2(q0, q1);
            // y' = (P y) + i (Q y)
            F2U U, Qv; U.u = up; Qv.u = uq;
            y = pk2(U.f.x - Qv.f.y, U.f.y + Qv.f.x);

            nx0[p + 6] = y;
            nx1[p + 7] = y;
            __syncthreads();
            u64* t0_ = cur0; cur0 = nx0; nx0 = t0_;
            u64* t1_ = cur1; cur1 = nx1; nx1 = t1_;
        }
        if (p < NPTS) {
            int row = (itv + 1) * NPTS + p;
            out[row]        = lo2(y);
            out[half + row] = hi2(y);
        }
    }
}

extern "C" void kernel_launch(void* const* d_in, const int* in_sizes, int n_in,
                              void* d_out, int out_size)
{
    int p_idx = 1, t_idx = 0;
    if (n_in >= 2 && in_sizes[0] == 2 && in_sizes[1] != 2) { p_idx = 0; t_idx = 1; }
    const float* params = (const float*)d_in[p_idx];
    const int n_save = in_sizes[t_idx];
    pe_kernel<<<1, NTH>>>(params, (float*)d_out, n_save);
}